// round 1
// baseline (speedup 1.0000x reference)
#include <cuda_runtime.h>
#include <cuda_bf16.h>
#include <cstdint>

// Shapes (fixed for this problem)
#define B_  8
#define T_  2048
#define C_  1024
#define NH  16
#define HS  64
#define NG  8
#define GT  256        // tokens per group
#define LQ  257        // GT + 1 mean token

// ---------------- device scratch (no allocations allowed) ----------------
__device__ float g_q[B_*NH*NG*GT*HS];     // 64 MB  [ (b,h,g), t, d ]
__device__ float g_k[B_*NH*NG*GT*HS];
__device__ float g_v[B_*NH*NG*GT*HS];
__device__ float g_qm[B_*NH*NG*HS];       // group means
__device__ float g_km[B_*NH*NG*HS];
__device__ float g_vm[B_*NH*NG*HS];
__device__ float g_attm[B_*NH*NG*HS];     // attention output at mean-token query
__device__ float g_xo[B_*T_*C_];          // 64 MB  [b, t, c] for proj GEMM

// ---------------- helpers ----------------
__device__ __forceinline__ float tf32r(float x) {
    unsigned r;
    asm("cvt.rna.tf32.f32 %0, %1;" : "=r"(r) : "f"(x));
    return __uint_as_float(r);
}

__device__ __forceinline__ void mma_tf32(float& c0, float& c1, float& c2, float& c3,
                                         unsigned a0, unsigned a1, unsigned a2, unsigned a3,
                                         unsigned b0, unsigned b1) {
    asm volatile(
        "mma.sync.aligned.m16n8k8.row.col.f32.tf32.tf32.f32 "
        "{%0,%1,%2,%3}, {%4,%5,%6,%7}, {%8,%9}, {%0,%1,%2,%3};\n"
        : "+f"(c0), "+f"(c1), "+f"(c2), "+f"(c3)
        : "r"(a0), "r"(a1), "r"(a2), "r"(a3), "r"(b0), "r"(b1));
}

// ---------------- GEMM: C[M,N] = A[M,K] * B[K,N], K=1024 ----------------
// mode 0: A = x, B = W_attn (N=3072), epilogue scatters into g_q/g_k/g_v
// mode 1: A = g_xo, B = W_proj (N=1024), epilogue writes row-major to Cout
__global__ __launch_bounds__(256)
void gemm_tf32_kernel(const float* __restrict__ A, const float* __restrict__ Bm,
                      float* __restrict__ Cout, int N, int mode) {
    const int K = 1024;
    __shared__ float As[16][132];   // [k][m], tf32-rounded
    __shared__ float Bs[16][132];   // [k][n], tf32-rounded

    const int tid  = threadIdx.x;
    const int warp = tid >> 5;
    const int lane = tid & 31;
    const int wm   = warp & 3;      // 4 warps along M
    const int wn   = warp >> 2;     // 2 warps along N
    const int bm   = blockIdx.x * 128;
    const int bn   = blockIdx.y * 128;

    const float* Ap = (mode == 0) ? A : (const float*)g_xo;

    float acc[2][8][4];
#pragma unroll
    for (int mt = 0; mt < 2; mt++)
#pragma unroll
        for (int nt = 0; nt < 8; nt++)
#pragma unroll
            for (int i = 0; i < 4; i++) acc[mt][nt][i] = 0.f;

    for (int k0 = 0; k0 < K; k0 += 16) {
        // A tile: 128 rows x 16 cols -> store transposed As[k][m]
#pragma unroll
        for (int u = 0; u < 2; u++) {
            int f  = tid * 2 + u;          // 512 float4
            int r  = f >> 2;               // 4 float4 per row
            int cb = f & 3;
            float4 va = *reinterpret_cast<const float4*>(Ap + (size_t)(bm + r) * K + k0 + cb * 4);
            As[cb * 4 + 0][r] = tf32r(va.x);
            As[cb * 4 + 1][r] = tf32r(va.y);
            As[cb * 4 + 2][r] = tf32r(va.z);
            As[cb * 4 + 3][r] = tf32r(va.w);
        }
        // B tile: 16 rows x 128 cols -> Bs[k][n]
#pragma unroll
        for (int u = 0; u < 2; u++) {
            int f  = tid * 2 + u;
            int r  = f >> 5;               // 32 float4 per row
            int cb = f & 31;
            float4 vb = *reinterpret_cast<const float4*>(Bm + (size_t)(k0 + r) * N + bn + cb * 4);
            float4 o;
            o.x = tf32r(vb.x); o.y = tf32r(vb.y); o.z = tf32r(vb.z); o.w = tf32r(vb.w);
            *reinterpret_cast<float4*>(&Bs[r][cb * 4]) = o;
        }
        __syncthreads();

#pragma unroll
        for (int ks = 0; ks < 2; ks++) {
            unsigned af[2][4];
            unsigned bf[8][2];
#pragma unroll
            for (int mt = 0; mt < 2; mt++) {
                int row = wm * 32 + mt * 16 + (lane >> 2);
                int col = ks * 8 + (lane & 3);
                af[mt][0] = __float_as_uint(As[col    ][row    ]);
                af[mt][1] = __float_as_uint(As[col    ][row + 8]);
                af[mt][2] = __float_as_uint(As[col + 4][row    ]);
                af[mt][3] = __float_as_uint(As[col + 4][row + 8]);
            }
#pragma unroll
            for (int nt = 0; nt < 8; nt++) {
                int col = wn * 64 + nt * 8 + (lane >> 2);
                int row = ks * 8 + (lane & 3);
                bf[nt][0] = __float_as_uint(Bs[row    ][col]);
                bf[nt][1] = __float_as_uint(Bs[row + 4][col]);
            }
#pragma unroll
            for (int mt = 0; mt < 2; mt++)
#pragma unroll
                for (int nt = 0; nt < 8; nt++)
                    mma_tf32(acc[mt][nt][0], acc[mt][nt][1], acc[mt][nt][2], acc[mt][nt][3],
                             af[mt][0], af[mt][1], af[mt][2], af[mt][3],
                             bf[nt][0], bf[nt][1]);
        }
        __syncthreads();
    }

    // Epilogue
#pragma unroll
    for (int mt = 0; mt < 2; mt++)
#pragma unroll
        for (int nt = 0; nt < 8; nt++)
#pragma unroll
            for (int i = 0; i < 4; i++) {
                int r = bm + wm * 32 + mt * 16 + (lane >> 2) + ((i & 2) ? 8 : 0);
                int c = bn + wn * 64 + nt * 8 + (lane & 3) * 2 + (i & 1);
                float v = acc[mt][nt][i];
                if (mode == 0) {
                    int b = r >> 11, tg = r & 2047;
                    int g = tg >> 8, t = tg & 255;
                    int which = c >> 10, cc = c & 1023;
                    int h = cc >> 6, d = cc & 63;
                    size_t o = ((((size_t)b * NH + h) * NG + g) * GT + t) * HS + d;
                    float* dst = (which == 0) ? g_q : (which == 1) ? g_k : g_v;
                    dst[o] = v;
                } else {
                    Cout[(size_t)r * N + c] = v;
                }
            }
}

// ---------------- group means ----------------
// grid = B*NH*NG (1024), block 192: threads [0,64)=q, [64,128)=k, [128,192)=v
__global__ void means_kernel() {
    int id = blockIdx.x;
    int d = threadIdx.x & 63;
    int which = threadIdx.x >> 6;
    const float* src = (which == 0) ? g_q : (which == 1) ? g_k : g_v;
    float* dst = (which == 0) ? g_qm : (which == 1) ? g_km : g_vm;
    size_t base = (size_t)id * (GT * HS);
    float s = 0.f;
#pragma unroll 8
    for (int t = 0; t < GT; t++) s += src[base + t * HS + d];
    dst[(size_t)id * HS + d] = s * (1.f / 256.f);
}

// ---------------- level-1 causal attention over 257 tokens ----------------
// grid = B*NH*NG (1024), block 256. Token 256 = group mean.
__global__ __launch_bounds__(256)
void attn_kernel() {
    extern __shared__ float sm[];
    float* Qs = sm;                        // 257 x 65 (padded)
    float* Ks = Qs + LQ * 65;
    float* Vs = Ks + LQ * 65;
    float* Ws = Vs + LQ * 65;              // 8 warps x 257 weights

    const int id = blockIdx.x;             // (b*16+h)*8+g
    const int g = id & 7, h = (id >> 3) & 15, b = id >> 7;
    const int tid = threadIdx.x;
    const int warp = tid >> 5, lane = tid & 31;

    size_t off = (size_t)id * (GT * HS);
    for (int idx = tid; idx < GT * HS; idx += 256) {
        int t = idx >> 6, d = idx & 63;
        Qs[t * 65 + d] = g_q[off + idx];
        Ks[t * 65 + d] = g_k[off + idx];
        Vs[t * 65 + d] = g_v[off + idx];
    }
    if (tid < HS) {
        Qs[256 * 65 + tid] = g_qm[(size_t)id * HS + tid];
        Ks[256 * 65 + tid] = g_km[(size_t)id * HS + tid];
        Vs[256 * 65 + tid] = g_vm[(size_t)id * HS + tid];
    }
    __syncthreads();

    for (int i = warp; i < LQ; i += 8) {
        const float* qp = Qs + i * 65;
        float mx = -1e30f;
        for (int j = lane; j <= i; j += 32) {
            const float* kp = Ks + j * 65;
            float s = 0.f;
#pragma unroll
            for (int dd = 0; dd < HS; dd++) s += qp[dd] * kp[dd];
            s *= 0.125f;
            Ws[warp * LQ + j] = s;
            mx = fmaxf(mx, s);
        }
#pragma unroll
        for (int o = 16; o; o >>= 1) mx = fmaxf(mx, __shfl_xor_sync(0xffffffffu, mx, o));
        float sum = 0.f;
        for (int j = lane; j <= i; j += 32) {
            float e = __expf(Ws[warp * LQ + j] - mx);
            Ws[warp * LQ + j] = e;
            sum += e;
        }
#pragma unroll
        for (int o = 16; o; o >>= 1) sum += __shfl_xor_sync(0xffffffffu, sum, o);
        float inv = 1.f / sum;
        __syncwarp();

        float acc0 = 0.f, acc1 = 0.f;
        for (int j = 0; j <= i; j++) {
            float w = Ws[warp * LQ + j];
            acc0 += w * Vs[j * 65 + lane];
            acc1 += w * Vs[j * 65 + lane + 32];
        }
        acc0 *= inv; acc1 *= inv;

        if (i < GT) {
            size_t o = ((size_t)b * T_ + g * GT + i) * C_ + h * HS;
            g_xo[o + lane]      = acc0;
            g_xo[o + lane + 32] = acc1;
        } else {
            g_attm[(size_t)id * HS + lane]      = acc0;
            g_attm[(size_t)id * HS + lane + 32] = acc1;
        }
        __syncwarp();
    }
}

// ---------------- level-2 tiny 7x7 causal attention + y outputs ----------------
// grid = B*NH (128), block 64
__global__ void second_kernel(float* __restrict__ out) {
    __shared__ float q7[7][64], k7[7][64], a7[7][64];
    __shared__ float S[7][8], W[7][8];
    const int id = blockIdx.x;            // b*16+h
    const int tid = threadIdx.x;

    for (int idx = tid; idx < 7 * 64; idx += 64) {
        int j = idx >> 6, d = idx & 63;
        q7[j][d] = g_qm[((size_t)id * NG + j) * HS + d];
        k7[j][d] = g_km[((size_t)id * NG + j) * HS + d];
        a7[j][d] = g_attm[((size_t)id * NG + j) * HS + d];
    }
    __syncthreads();

    if (tid < 28) {
        int p = tid, j = 0;
        while ((j + 1) * (j + 2) / 2 <= p) j++;
        int jp = p - j * (j + 1) / 2;
        float s = 0.f;
#pragma unroll
        for (int dd = 0; dd < 64; dd++) s += q7[j][dd] * k7[jp][dd];
        S[j][jp] = s * 0.125f;
    }
    __syncthreads();

    if (tid < 7) {
        int j = tid;
        float mx = -1e30f;
        for (int jp = 0; jp <= j; jp++) mx = fmaxf(mx, S[j][jp]);
        float sum = 0.f;
        for (int jp = 0; jp <= j; jp++) { float e = __expf(S[j][jp] - mx); W[j][jp] = e; sum += e; }
        float inv = 1.f / sum;
        for (int jp = 0; jp <= j; jp++) W[j][jp] *= inv;
    }
    __syncthreads();

    const size_t yq_off = (size_t)B_ * T_ * C_;       // 16,777,216
    const size_t ylen   = (size_t)B_ * NH * 7 * HS;   // 57,344
    int d = tid;                                      // 64 threads, one dim each
    for (int j = 0; j < 7; j++) {
        float acc = 0.f;
        for (int jp = 0; jp <= j; jp++) acc += W[j][jp] * a7[jp][d];
        size_t o = ((size_t)id * 7 + j) * HS + d;
        out[yq_off            + o] = q7[j][d];
        out[yq_off +     ylen + o] = k7[j][d];
        out[yq_off + 2 * ylen + o] = acc;
    }
}

// ---------------- launch ----------------
extern "C" void kernel_launch(void* const* d_in, const int* in_sizes, int n_in,
                              void* d_out, int out_size) {
    (void)in_sizes; (void)n_in; (void)out_size;
    const float* x      = (const float*)d_in[0];
    const float* W_attn = (const float*)d_in[1];
    const float* W_proj = (const float*)d_in[2];
    float* out = (float*)d_out;

    // qkv = x @ W_attn  (M=16384, N=3072)
    gemm_tf32_kernel<<<dim3(128, 24), 256>>>(x, W_attn, nullptr, 3 * C_, 0);

    // group means of q,k,v
    means_kernel<<<B_ * NH * NG, 192>>>();

    // level-1 attention (257 tokens incl. mean)
    const int att_smem = (3 * LQ * 65 + 8 * LQ) * (int)sizeof(float);  // 208,684 B
    cudaFuncSetAttribute(attn_kernel, cudaFuncAttributeMaxDynamicSharedMemorySize, att_smem);
    attn_kernel<<<B_ * NH * NG, 256, att_smem>>>();

    // level-2 attention + yq/yk/yv outputs
    second_kernel<<<B_ * NH, 64>>>(out);

    // out = xo @ W_proj  (M=16384, N=1024)
    gemm_tf32_kernel<<<dim3(128, 8), 256>>>(nullptr, W_proj, out, C_, 1);
}

// round 4
// speedup vs baseline: 1.1661x; 1.1661x over previous
#include <cuda_runtime.h>
#include <cuda_bf16.h>
#include <cstdint>

// Shapes (fixed for this problem)
#define B_  8
#define T_  2048
#define C_  1024
#define NH  16
#define HS  64
#define NG  8
#define GT  256        // tokens per group
#define LQ  257        // GT + 1 mean token

// ---------------- device scratch (no allocations allowed) ----------------
__device__ float g_q[B_*NH*NG*GT*HS];
__device__ float g_k[B_*NH*NG*GT*HS];
__device__ float g_v[B_*NH*NG*GT*HS];
__device__ float g_qm[B_*NH*NG*HS];
__device__ float g_km[B_*NH*NG*HS];
__device__ float g_vm[B_*NH*NG*HS];
__device__ float g_attm[B_*NH*NG*HS];
__device__ float g_xo[B_*T_*C_];          // attn output (tf32-rounded), A of proj GEMM
__device__ float g_xr[B_*T_*C_];          // tf32-rounded x
__device__ float g_War[3*C_*C_];          // tf32-rounded W_attn [1024][3072]
__device__ float g_WpR[C_*C_];            // tf32-rounded W_proj [1024][1024]

// ---------------- helpers ----------------
__device__ __forceinline__ float tf32r(float x) {
    unsigned r;
    asm("cvt.rna.tf32.f32 %0, %1;" : "=r"(r) : "f"(x));
    return __uint_as_float(r);
}

__device__ __forceinline__ uint32_t smem_u32(const void* p) {
    uint32_t a;
    asm("{ .reg .u64 t; cvta.to.shared.u64 t, %1; cvt.u32.u64 %0, t; }" : "=r"(a) : "l"(p));
    return a;
}

__device__ __forceinline__ void cp16(uint32_t dst, const void* src) {
    asm volatile("cp.async.cg.shared.global [%0], [%1], 16;\n" :: "r"(dst), "l"(src));
}
#define CP_COMMIT() asm volatile("cp.async.commit_group;\n" ::: "memory")
#define CP_WAIT(n)  asm volatile("cp.async.wait_group %0;\n" :: "n"(n) : "memory")

__device__ __forceinline__ void mma_tf32(float& c0, float& c1, float& c2, float& c3,
                                         float a0, float a1, float a2, float a3,
                                         float b0, float b1) {
    asm volatile(
        "mma.sync.aligned.m16n8k8.row.col.f32.tf32.tf32.f32 "
        "{%0,%1,%2,%3}, {%4,%5,%6,%7}, {%8,%9}, {%0,%1,%2,%3};\n"
        : "+f"(c0), "+f"(c1), "+f"(c2), "+f"(c3)
        : "r"(__float_as_uint(a0)), "r"(__float_as_uint(a1)),
          "r"(__float_as_uint(a2)), "r"(__float_as_uint(a3)),
          "r"(__float_as_uint(b0)), "r"(__float_as_uint(b1)));
}

// ---------------- pre-rounding kernels (elementwise) ----------------
// which: 0 -> g_xr, 1 -> g_War, 2 -> g_WpR   (device globals resolved in device code!)
__global__ void round_kernel(const float* __restrict__ src, int which) {
    float* dst = (which == 0) ? g_xr : (which == 1) ? g_War : g_WpR;
    int i = (blockIdx.x * 256 + threadIdx.x) * 4;
    float4 v = *reinterpret_cast<const float4*>(src + i);
    v.x = tf32r(v.x); v.y = tf32r(v.y); v.z = tf32r(v.z); v.w = tf32r(v.w);
    *reinterpret_cast<float4*>(dst + i) = v;
}

// ---------------- pipelined tf32 GEMM: C[M,N] = A[M,K=1024] @ B[K,N] ----------------
// mode 0: A=g_xr, B=g_War (N=3072), epilogue scatters into g_q/g_k/g_v
// mode 1: A=g_xo, B=g_WpR (N=1024), epilogue writes row-major to Cout
#define BK 32
#define KCHUNKS 32                 // 1024 / 32
#define STAGES 3
#define A_STRIDE 36                // floats per A row
#define B_STRIDE 136               // floats per B row
#define A_STG (128 * A_STRIDE)     // 4608 floats
#define B_STG (BK * B_STRIDE)      // 4352 floats
#define STG_FLOATS (A_STG + B_STG) // 8960 floats = 35840 B

__global__ __launch_bounds__(256, 2)
void gemm_tf32_kernel(float* __restrict__ Cout, int N, int mode) {
    extern __shared__ float smemf[];
    const uint32_t smem_b = smem_u32(smemf);

    const float* __restrict__ A  = (mode == 0) ? g_xr  : g_xo;
    const float* __restrict__ Bm = (mode == 0) ? g_War : g_WpR;

    const int tid  = threadIdx.x;
    const int warp = tid >> 5;
    const int lane = tid & 31;
    const int wm   = warp & 1;      // 2 warps along M (64 each)
    const int wn   = warp >> 1;     // 4 warps along N (32 each)
    const int bm   = blockIdx.x * 128;
    const int bn   = blockIdx.y * 128;

    float acc[4][4][4];
#pragma unroll
    for (int mt = 0; mt < 4; mt++)
#pragma unroll
        for (int nt = 0; nt < 4; nt++)
#pragma unroll
            for (int i = 0; i < 4; i++) acc[mt][nt][i] = 0.f;

    // per-thread copy coordinates (A: 4 float4, B: 4 float4 per chunk)
    const int ar0 = tid >> 1;                 // 2 threads per A row
    const int as0 = (tid & 1) * 4;            // this thread does segs as0..as0+3
    const int br0 = tid >> 3;                 // 8 threads per B row (32 rows)
    const int bs0 = (tid & 7) * 4;            // this thread does segs bs0..bs0+3

    auto issue_copy = [&](int c, int s) {
        const int k0 = c * BK;
        const uint32_t sa = smem_b + (uint32_t)(s * STG_FLOATS) * 4u;
        const uint32_t sb = sa + (uint32_t)A_STG * 4u;
        const float* Asrc = A + (size_t)(bm + ar0) * 1024 + k0 + as0 * 4;
#pragma unroll
        for (int u = 0; u < 4; u++)
            cp16(sa + (uint32_t)(ar0 * A_STRIDE + (as0 + u) * 4) * 4u, Asrc + u * 4);
        const float* Bsrc = Bm + (size_t)(k0 + br0) * N + bn + bs0 * 4;
#pragma unroll
        for (int u = 0; u < 4; u++)
            cp16(sb + (uint32_t)(br0 * B_STRIDE + (bs0 + u) * 4) * 4u, Bsrc + u * 4);
        CP_COMMIT();
    };

    issue_copy(0, 0);
    issue_copy(1, 1);

    int stage = 0;
    for (int c = 0; c < KCHUNKS; c++) {
        if (c + 2 < KCHUNKS) { CP_WAIT(1); } else { CP_WAIT(0); }   // tail must drain fully
        __syncthreads();
        if (c + 2 < KCHUNKS) {
            int ns = stage + 2; if (ns >= STAGES) ns -= STAGES;
            issue_copy(c + 2, ns);
        }

        const float* As = smemf + stage * STG_FLOATS;
        const float* Bs = As + A_STG;

#pragma unroll
        for (int ks = 0; ks < 4; ks++) {
            float af[4][4];
            float bf[4][2];
            const int acol = ks * 8 + (lane & 3);
#pragma unroll
            for (int mt = 0; mt < 4; mt++) {
                const int row = wm * 64 + mt * 16 + (lane >> 2);
                af[mt][0] = As[row * A_STRIDE + acol];
                af[mt][1] = As[(row + 8) * A_STRIDE + acol];
                af[mt][2] = As[row * A_STRIDE + acol + 4];
                af[mt][3] = As[(row + 8) * A_STRIDE + acol + 4];
            }
            const int krow = ks * 8 + (lane & 3);
#pragma unroll
            for (int nt = 0; nt < 4; nt++) {
                const int ncol = wn * 32 + nt * 8 + (lane >> 2);
                bf[nt][0] = Bs[krow * B_STRIDE + ncol];
                bf[nt][1] = Bs[(krow + 4) * B_STRIDE + ncol];
            }
#pragma unroll
            for (int mt = 0; mt < 4; mt++)
#pragma unroll
                for (int nt = 0; nt < 4; nt++)
                    mma_tf32(acc[mt][nt][0], acc[mt][nt][1], acc[mt][nt][2], acc[mt][nt][3],
                             af[mt][0], af[mt][1], af[mt][2], af[mt][3],
                             bf[nt][0], bf[nt][1]);
        }
        __syncthreads();
        stage++; if (stage >= STAGES) stage = 0;
    }

    // ---- epilogue: float2 stores (cols (lane&3)*2, +1) ----
#pragma unroll
    for (int mt = 0; mt < 4; mt++) {
#pragma unroll
        for (int i2 = 0; i2 < 2; i2++) {          // c0c1 (row) / c2c3 (row+8)
            const int r = bm + wm * 64 + mt * 16 + (lane >> 2) + i2 * 8;
#pragma unroll
            for (int nt = 0; nt < 4; nt++) {
                const int c = bn + wn * 32 + nt * 8 + (lane & 3) * 2;
                float2 v = make_float2(acc[mt][nt][i2 * 2], acc[mt][nt][i2 * 2 + 1]);
                if (mode == 0) {
                    const int which = c >> 10, cc = c & 1023;
                    const int h = cc >> 6, d0 = cc & 63;
                    const int b = r >> 11, tg = r & 2047, g = tg >> 8, t = tg & 255;
                    float* base = (which == 0) ? g_q : (which == 1) ? g_k : g_v;
                    *reinterpret_cast<float2*>(
                        base + ((((size_t)b * NH + h) * NG + g) * GT + t) * HS + d0) = v;
                } else {
                    *reinterpret_cast<float2*>(Cout + (size_t)r * N + c) = v;
                }
            }
        }
    }
}

// ---------------- group means ----------------
__global__ void means_kernel() {
    int id = blockIdx.x;
    int d = threadIdx.x & 63;
    int which = threadIdx.x >> 6;
    const float* src = (which == 0) ? g_q : (which == 1) ? g_k : g_v;
    float* dst = (which == 0) ? g_qm : (which == 1) ? g_km : g_vm;
    size_t base = (size_t)id * (GT * HS);
    float s = 0.f;
#pragma unroll 8
    for (int t = 0; t < GT; t++) s += src[base + t * HS + d];
    dst[(size_t)id * HS + d] = s * (1.f / 256.f);
}

// ---------------- level-1 causal attention over 257 tokens ----------------
__global__ __launch_bounds__(256)
void attn_kernel() {
    extern __shared__ float sm[];
    float* Qs = sm;
    float* Ks = Qs + LQ * 65;
    float* Vs = Ks + LQ * 65;
    float* Ws = Vs + LQ * 65;

    const int id = blockIdx.x;
    const int g = id & 7, h = (id >> 3) & 15, b = id >> 7;
    const int tid = threadIdx.x;
    const int warp = tid >> 5, lane = tid & 31;

    size_t off = (size_t)id * (GT * HS);
    for (int idx = tid; idx < GT * HS; idx += 256) {
        int t = idx >> 6, d = idx & 63;
        Qs[t * 65 + d] = g_q[off + idx];
        Ks[t * 65 + d] = g_k[off + idx];
        Vs[t * 65 + d] = g_v[off + idx];
    }
    if (tid < HS) {
        Qs[256 * 65 + tid] = g_qm[(size_t)id * HS + tid];
        Ks[256 * 65 + tid] = g_km[(size_t)id * HS + tid];
        Vs[256 * 65 + tid] = g_vm[(size_t)id * HS + tid];
    }
    __syncthreads();

    for (int i = warp; i < LQ; i += 8) {
        const float* qp = Qs + i * 65;
        float mx = -1e30f;
        for (int j = lane; j <= i; j += 32) {
            const float* kp = Ks + j * 65;
            float s = 0.f;
#pragma unroll
            for (int dd = 0; dd < HS; dd++) s += qp[dd] * kp[dd];
            s *= 0.125f;
            Ws[warp * LQ + j] = s;
            mx = fmaxf(mx, s);
        }
#pragma unroll
        for (int o = 16; o; o >>= 1) mx = fmaxf(mx, __shfl_xor_sync(0xffffffffu, mx, o));
        float sum = 0.f;
        for (int j = lane; j <= i; j += 32) {
            float e = __expf(Ws[warp * LQ + j] - mx);
            Ws[warp * LQ + j] = e;
            sum += e;
        }
#pragma unroll
        for (int o = 16; o; o >>= 1) sum += __shfl_xor_sync(0xffffffffu, sum, o);
        float inv = 1.f / sum;
        __syncwarp();

        float acc0 = 0.f, acc1 = 0.f;
        for (int j = 0; j <= i; j++) {
            float w = Ws[warp * LQ + j];
            acc0 += w * Vs[j * 65 + lane];
            acc1 += w * Vs[j * 65 + lane + 32];
        }
        acc0 *= inv; acc1 *= inv;

        if (i < GT) {
            size_t o = ((size_t)b * T_ + g * GT + i) * C_ + h * HS;
            g_xo[o + lane]      = tf32r(acc0);
            g_xo[o + lane + 32] = tf32r(acc1);
        } else {
            g_attm[(size_t)id * HS + lane]      = acc0;
            g_attm[(size_t)id * HS + lane + 32] = acc1;
        }
        __syncwarp();
    }
}

// ---------------- level-2 tiny 7x7 causal attention + y outputs ----------------
__global__ void second_kernel(float* __restrict__ out) {
    __shared__ float q7[7][64], k7[7][64], a7[7][64];
    __shared__ float S[7][8], W[7][8];
    const int id = blockIdx.x;
    const int tid = threadIdx.x;

    for (int idx = tid; idx < 7 * 64; idx += 64) {
        int j = idx >> 6, d = idx & 63;
        q7[j][d] = g_qm[((size_t)id * NG + j) * HS + d];
        k7[j][d] = g_km[((size_t)id * NG + j) * HS + d];
        a7[j][d] = g_attm[((size_t)id * NG + j) * HS + d];
    }
    __syncthreads();

    if (tid < 28) {
        int p = tid, j = 0;
        while ((j + 1) * (j + 2) / 2 <= p) j++;
        int jp = p - j * (j + 1) / 2;
        float s = 0.f;
#pragma unroll
        for (int dd = 0; dd < 64; dd++) s += q7[j][dd] * k7[jp][dd];
        S[j][jp] = s * 0.125f;
    }
    __syncthreads();

    if (tid < 7) {
        int j = tid;
        float mx = -1e30f;
        for (int jp = 0; jp <= j; jp++) mx = fmaxf(mx, S[j][jp]);
        float sum = 0.f;
        for (int jp = 0; jp <= j; jp++) { float e = __expf(S[j][jp] - mx); W[j][jp] = e; sum += e; }
        float inv = 1.f / sum;
        for (int jp = 0; jp <= j; jp++) W[j][jp] *= inv;
    }
    __syncthreads();

    const size_t yq_off = (size_t)B_ * T_ * C_;
    const size_t ylen   = (size_t)B_ * NH * 7 * HS;
    int d = tid;
    for (int j = 0; j < 7; j++) {
        float acc = 0.f;
        for (int jp = 0; jp <= j; jp++) acc += W[j][jp] * a7[jp][d];
        size_t o = ((size_t)id * 7 + j) * HS + d;
        out[yq_off            + o] = q7[j][d];
        out[yq_off +     ylen + o] = k7[j][d];
        out[yq_off + 2 * ylen + o] = acc;
    }
}

// ---------------- launch ----------------
extern "C" void kernel_launch(void* const* d_in, const int* in_sizes, int n_in,
                              void* d_out, int out_size) {
    (void)in_sizes; (void)n_in; (void)out_size;
    const float* x      = (const float*)d_in[0];
    const float* W_attn = (const float*)d_in[1];
    const float* W_proj = (const float*)d_in[2];
    float* out = (float*)d_out;

    // pre-round to tf32 (HMMA truncates; round-to-nearest halves the error)
    round_kernel<<<B_*T_*C_/1024, 256>>>(x, 0);
    round_kernel<<<3*C_*C_/1024, 256>>>(W_attn, 1);
    round_kernel<<<C_*C_/1024, 256>>>(W_proj, 2);

    const int gemm_smem = STAGES * STG_FLOATS * (int)sizeof(float);   // 107520
    cudaFuncSetAttribute(gemm_tf32_kernel, cudaFuncAttributeMaxDynamicSharedMemorySize, gemm_smem);

    // qkv = x @ W_attn  (M=16384, N=3072)
    gemm_tf32_kernel<<<dim3(128, 24), 256, gemm_smem>>>(nullptr, 3 * C_, 0);

    means_kernel<<<B_ * NH * NG, 192>>>();

    const int att_smem = (3 * LQ * 65 + 8 * LQ) * (int)sizeof(float);
    cudaFuncSetAttribute(attn_kernel, cudaFuncAttributeMaxDynamicSharedMemorySize, att_smem);
    attn_kernel<<<B_ * NH * NG, 256, att_smem>>>();

    second_kernel<<<B_ * NH, 64>>>(out);

    // out = xo @ W_proj  (M=16384, N=1024)
    gemm_tf32_kernel<<<dim3(128, 8), 256, gemm_smem>>>(out, C_, 1);
}